// round 4
// baseline (speedup 1.0000x reference)
#include <cuda_runtime.h>
#include <math.h>

#define FULLMASK 0xffffffffu
#define Bn   64
#define Wn   128
#define Fn   132
#define An   128
#define TGTn 3
#define En   8
#define HIDn 16
#define OUTn 128
#define NROW (Bn*Wn)

typedef unsigned long long u64;

// ---------------- scratch (device globals; no allocation) ----------------
__device__ float g_Lo[NROW*En];
__device__ float g_Ro[NROW*En];
__device__ float g_hL[NROW*HIDn];
__device__ float g_hR[NROW*HIDn];
__device__ float g_bn[2][2][HIDn];
__device__ float g_xw0[NROW*48];
__device__ float g_h1fin[Bn*HIDn];
__device__ float g_dech[Bn*HIDn];

// exact activations (mixer — precision-critical path)
__device__ __forceinline__ float sigm_x(float x) { return 1.0f / (1.0f + __expf(-x)); }
__device__ __forceinline__ float tanh_x(float x) { return fmaf(2.0f, sigm_x(2.0f * x), -1.0f); }
// HW-approx activations (gate — smoothed by softmax downstream)
__device__ __forceinline__ float tanh_a(float x) {
    float y; asm("tanh.approx.f32 %0, %1;" : "=f"(y) : "f"(x)); return y;
}
__device__ __forceinline__ float sigm_a(float x) { return fmaf(0.5f, tanh_a(0.5f * x), 0.5f); }

// packed f32x2 helpers
__device__ __forceinline__ u64 pack2(float lo, float hi) {
    u64 r; asm("mov.b64 %0, {%1,%2};" : "=l"(r) : "f"(lo), "f"(hi)); return r;
}
__device__ __forceinline__ void unpack2(u64 v, float& lo, float& hi) {
    asm("mov.b64 {%0,%1}, %2;" : "=f"(lo), "=f"(hi) : "l"(v));
}
__device__ __forceinline__ u64 ffma2(u64 a, u64 b, u64 c) {
    u64 d; asm("fma.rn.f32x2 %0, %1, %2, %3;" : "=l"(d) : "l"(a), "l"(b), "l"(c)); return d;
}

// ============================================================================
// K1: gate GRU (2 layers, H=8) + softmax. One warp per (side,batch).
// ============================================================================
__global__ void __launch_bounds__(32) k_gate(
    const float* __restrict__ Local, const float* __restrict__ Remote,
    const float* __restrict__ Wih0, const float* __restrict__ Whh0,
    const float* __restrict__ bih0, const float* __restrict__ bhh0,
    const float* __restrict__ Wih1, const float* __restrict__ Whh1,
    const float* __restrict__ bih1, const float* __restrict__ bhh1)
{
    const int lane = threadIdx.x;
    const int side = blockIdx.x >> 6;
    const int b    = blockIdx.x & 63;
    const float* in  = side ? Remote : Local;
    float*       out = side ? g_Ro   : g_Lo;

    float wa=0.f, wb=0.f, wc=0.f, bi0=0.f, bh0=0.f, bi1=0.f, bh1=0.f;
    float u0[8], wi1[8], u1[8];
#pragma unroll
    for (int k = 0; k < 8; k++) { u0[k]=0.f; wi1[k]=0.f; u1[k]=0.f; }
    if (lane < 24) {
        wa = Wih0[lane*3+0]; wb = Wih0[lane*3+1]; wc = Wih0[lane*3+2];
        bi0 = bih0[lane]; bh0 = bhh0[lane];
        bi1 = bih1[lane]; bh1 = bhh1[lane];
#pragma unroll
        for (int k = 0; k < 8; k++) {
            u0[k]  = Whh0[lane*8+k];
            wi1[k] = Wih1[lane*8+k];
            u1[k]  = Whh1[lane*8+k];
        }
    }

    float h0[8], h1[8];
#pragma unroll
    for (int j = 0; j < 8; j++) { h0[j]=0.f; h1[j]=0.f; }

    const float* px = in + (size_t)b * Wn * Fn + An;
    float x0 = px[0], x1 = px[1], x2 = px[2];

    for (int t = 0; t < Wn; t++) {
        float cx0 = x0, cx1 = x1, cx2 = x2;
        if (t + 1 < Wn) {
            const float* pn = px + (size_t)(t + 1) * Fn;
            x0 = pn[0]; x1 = pn[1]; x2 = pn[2];
        }
        // layer 0 (split 2-chain dot)
        float xw = fmaf(wa, cx0, fmaf(wb, cx1, fmaf(wc, cx2, bi0)));
        float ga = fmaf(u0[0],h0[0], fmaf(u0[2],h0[2], fmaf(u0[4],h0[4], fmaf(u0[6],h0[6], bh0))));
        float gb = fmaf(u0[1],h0[1], fmaf(u0[3],h0[3], fmaf(u0[5],h0[5], u0[7]*h0[7])));
        float gh = ga + gb;
        float s  = sigm_a(xw + gh);
        float r  = __shfl_sync(FULLMASK, s, lane & 7);
        float nv = tanh_a(fmaf(r, gh, xw));
#pragma unroll
        for (int j = 0; j < 8; j++) {
            float z = __shfl_sync(FULLMASK, s,  8 + j);
            float n = __shfl_sync(FULLMASK, nv, 16 + j);
            h0[j] = fmaf(z, h0[j] - n, n);
        }
        // layer 1
        float xa = fmaf(wi1[0],h0[0], fmaf(wi1[2],h0[2], fmaf(wi1[4],h0[4], fmaf(wi1[6],h0[6], bi1))));
        float xb = fmaf(wi1[1],h0[1], fmaf(wi1[3],h0[3], fmaf(wi1[5],h0[5], wi1[7]*h0[7])));
        float xw1 = xa + xb;
        float g1a = fmaf(u1[0],h1[0], fmaf(u1[2],h1[2], fmaf(u1[4],h1[4], fmaf(u1[6],h1[6], bh1))));
        float g1b = fmaf(u1[1],h1[1], fmaf(u1[3],h1[3], fmaf(u1[5],h1[5], u1[7]*h1[7])));
        float gh1 = g1a + g1b;
        float s1  = sigm_a(xw1 + gh1);
        float r1  = __shfl_sync(FULLMASK, s1, lane & 7);
        float nv1 = tanh_a(fmaf(r1, gh1, xw1));
#pragma unroll
        for (int j = 0; j < 8; j++) {
            float z = __shfl_sync(FULLMASK, s1,  8 + j);
            float n = __shfl_sync(FULLMASK, nv1, 16 + j);
            h1[j] = fmaf(z, h1[j] - n, n);
        }
        // softmax over replicated h1 (|h1|<1 -> no max-subtraction needed)
        float ex[8];
#pragma unroll
        for (int j = 0; j < 8; j++) ex[j] = __expf(h1[j]);
        float sA = (ex[0]+ex[1]) + (ex[2]+ex[3]);
        float sB = (ex[4]+ex[5]) + (ex[6]+ex[7]);
        float inv = __frcp_rn(sA + sB);
        if (lane < 8) {
            float v = ex[0];
#pragma unroll
            for (int j = 1; j < 8; j++) if (lane == j) v = ex[j];
            out[((size_t)b * Wn + t) * En + lane] = v * inv;
        }
    }
}

// ============================================================================
// K2: expert layer-1 with f32x2 FFMA. 256 blocks (side x 128 tiles of 64 rows),
// 256 threads = 64 rows x 4 h-quads. pe pairs are adjacent outputs -> no
// horizontal collapse; accumulation order per-output identical to scalar.
// ============================================================================
#define K2_SMEM_BYTES ((16384 + 64*129 + 512 + 128) * 4)
__global__ void __launch_bounds__(256) k_exp1(
    const float* __restrict__ Local, const float* __restrict__ Remote,
    const float* __restrict__ w1, const float* __restrict__ b1)
{
    extern __shared__ float sm[];
    float* sw1 = sm;                 // (E,A,HID) 16384
    float* sx  = sw1 + 16384;        // 64 x 129
    float* som = sx + 64 * 129;      // 64 x 8
    float* sb1 = som + 512;          // 128

    const int tid  = threadIdx.x;
    const int side = blockIdx.x >> 7;
    const int tile = blockIdx.x & 127;
    const int n0   = tile * 64;
    const float* in  = side ? Remote : Local;
    const float* om  = side ? g_Ro   : g_Lo;
    float*       dst = side ? g_hR   : g_hL;

    {
        const float4* w14 = (const float4*)w1;
        float4* sw14 = (float4*)sw1;
        for (int i = tid; i < 4096; i += 256) sw14[i] = w14[i];
        for (int i = tid; i < 64 * 128; i += 256) {
            int r = i >> 7, c = i & 127;
            sx[r * 129 + c] = in[(size_t)(n0 + r) * Fn + c];
        }
        for (int i = tid; i < 512; i += 256) som[i] = om[(size_t)n0 * En + i];
        if (tid < 128) sb1[tid] = b1[tid];
    }
    __syncthreads();

    const int r = tid >> 2;       // row 0..63
    const int q = tid & 3;        // h-quad
    const float* xrow = sx + r * 129;

    u64 acc0 = pack2(0.f, 0.f), acc1 = pack2(0.f, 0.f);

#pragma unroll 1
    for (int e = 0; e < 8; e++) {
        u64 p0 = pack2(sb1[e*16 + q*4 + 0], sb1[e*16 + q*4 + 1]);
        u64 p1 = pack2(sb1[e*16 + q*4 + 2], sb1[e*16 + q*4 + 3]);
        const ulonglong2* wq = (const ulonglong2*)(sw1 + e * 2048) + q;
#pragma unroll 4
        for (int i = 0; i < 128; i++) {
            float xv = xrow[i];
            u64 x2 = pack2(xv, xv);
            ulonglong2 w = wq[i * 4];
            p0 = ffma2(x2, w.x, p0);
            p1 = ffma2(x2, w.y, p1);
        }
        float oe = som[r * 8 + e];
        u64 o2 = pack2(oe, oe);
        acc0 = ffma2(o2, p0, acc0);
        acc1 = ffma2(o2, p1, acc1);
    }
    ulonglong2 outv; outv.x = acc0; outv.y = acc1;
    *(ulonglong2*)(dst + (size_t)(n0 + r) * 16 + q * 4) = outv;
}

// ============================================================================
// K2b: deterministic BN statistics. 32 blocks = (side,h), 256 threads.
// ============================================================================
__global__ void k_bnstat()
{
    __shared__ float ss[256], sq[256];
    const int side = blockIdx.x >> 4, h = blockIdx.x & 15, tid = threadIdx.x;
    const float* src = side ? g_hR : g_hL;
    float s = 0.f, q = 0.f;
    for (int r = tid; r < NROW; r += 256) {
        float v = src[(size_t)r * 16 + h];
        s += v; q = fmaf(v, v, q);
    }
    ss[tid] = s; sq[tid] = q;
    __syncthreads();
    for (int ofs = 128; ofs > 0; ofs >>= 1) {
        if (tid < ofs) { ss[tid] += ss[tid + ofs]; sq[tid] += sq[tid + ofs]; }
        __syncthreads();
    }
    if (tid == 0) { g_bn[side][0][h] = ss[0]; g_bn[side][1][h] = sq[0]; }
}

// ============================================================================
// K3: BN+elu, expert layer-2, Z=ZL+ZR, mixer layer-0 input projection.
// 128 blocks x 256 threads: thread = (row, expert-pair). 4 lanes/row,
// shfl-allreduce z, then each lane projects 12 of the 48 gate inputs.
// ============================================================================
__global__ void __launch_bounds__(256) k_exp2(
    const float* __restrict__ w2, const float* __restrict__ b2,
    const float* __restrict__ aeg, const float* __restrict__ aebt,
    const float* __restrict__ Wih0m, const float* __restrict__ bih0m)
{
    __shared__ float sw2[2048], sb2[128], sW[768], sbi[48], sg[16], sbt[16];
    __shared__ float sstat[2][2][16];
    const int tid = threadIdx.x;
    for (int i = tid; i < 2048; i += 256) sw2[i] = w2[i];
    for (int i = tid; i < 768;  i += 256) sW[i]  = Wih0m[i];
    if (tid < 128) sb2[tid] = b2[tid];
    if (tid < 48)  sbi[tid] = bih0m[tid];
    if (tid < 16)  { sg[tid] = aeg[tid]; sbt[tid] = aebt[tid]; }
    if (tid < 32) {
        int side = tid >> 4, h = tid & 15;
        float mean = g_bn[side][0][h] * (1.0f / NROW);
        float var  = g_bn[side][1][h] * (1.0f / NROW) - mean * mean;
        sstat[side][0][h] = mean;
        sstat[side][1][h] = rsqrtf(var + 1e-5f);
    }
    __syncthreads();

    const int g  = blockIdx.x * 256 + tid;
    const int n  = g >> 2;
    const int sl = g & 3;

    u64 zac[8];
#pragma unroll
    for (int j = 0; j < 8; j++) zac[j] = pack2(0.f, 0.f);

#pragma unroll 1
    for (int side = 0; side < 2; side++) {
        const float* hsrc = side ? g_hR : g_hL;
        const float* osrc = side ? g_Ro : g_Lo;
        float hv[16];
        const float4* hp = (const float4*)(hsrc + (size_t)n * 16);
#pragma unroll
        for (int q4 = 0; q4 < 4; q4++) {
            float4 v = hp[q4];
            hv[q4*4+0]=v.x; hv[q4*4+1]=v.y; hv[q4*4+2]=v.z; hv[q4*4+3]=v.w;
        }
#pragma unroll
        for (int h = 0; h < 16; h++) {
            float v = fmaf(sg[h] * (hv[h] - sstat[side][0][h]), sstat[side][1][h], sbt[h]);
            hv[h] = (v > 0.f) ? v : (__expf(v) - 1.0f);
        }
#pragma unroll
        for (int ei = 0; ei < 2; ei++) {
            int e = 2 * sl + ei;
            u64 pe[8];
#pragma unroll
            for (int j = 0; j < 8; j++) pe[j] = pack2(sb2[e*16 + 2*j], sb2[e*16 + 2*j + 1]);
            const ulonglong2* wr = (const ulonglong2*)(sw2 + e * 256);
#pragma unroll
            for (int h = 0; h < 16; h++) {
                u64 h2 = pack2(hv[h], hv[h]);
                ulonglong2 wA = wr[h*4 + 0];
                ulonglong2 wB = wr[h*4 + 1];
                ulonglong2 wC = wr[h*4 + 2];
                ulonglong2 wD = wr[h*4 + 3];
                pe[0] = ffma2(h2, wA.x, pe[0]); pe[1] = ffma2(h2, wA.y, pe[1]);
                pe[2] = ffma2(h2, wB.x, pe[2]); pe[3] = ffma2(h2, wB.y, pe[3]);
                pe[4] = ffma2(h2, wC.x, pe[4]); pe[5] = ffma2(h2, wC.y, pe[5]);
                pe[6] = ffma2(h2, wD.x, pe[6]); pe[7] = ffma2(h2, wD.y, pe[7]);
            }
            float oe = osrc[(size_t)n * 8 + e];
            u64 o2 = pack2(oe, oe);
#pragma unroll
            for (int j = 0; j < 8; j++) zac[j] = ffma2(o2, pe[j], zac[j]);
        }
    }

    // all-reduce z across the 4 expert-split lanes
    float zf[16];
#pragma unroll
    for (int j = 0; j < 8; j++) unpack2(zac[j], zf[2*j], zf[2*j+1]);
#pragma unroll
    for (int k = 0; k < 16; k++) {
        zf[k] += __shfl_xor_sync(FULLMASK, zf[k], 1);
        zf[k] += __shfl_xor_sync(FULLMASK, zf[k], 2);
    }
    u64 z2[8];
#pragma unroll
    for (int j = 0; j < 8; j++) z2[j] = pack2(zf[2*j], zf[2*j+1]);

    // mixer layer-0 input projection: 12 outputs per lane
    float* dst = g_xw0 + (size_t)n * 48 + sl * 12;
#pragma unroll
    for (int g3 = 0; g3 < 3; g3++) {
        float tmp[4];
#pragma unroll
        for (int qo = 0; qo < 4; qo++) {
            int o = sl * 12 + g3 * 4 + qo;
            const ulonglong2* wr = (const ulonglong2*)(sW + o * 16);
            u64 a0 = pack2(0.f, 0.f), a1 = pack2(0.f, 0.f);
            ulonglong2 wA = wr[0], wB = wr[1], wC = wr[2], wD = wr[3];
            a0 = ffma2(z2[0], wA.x, a0); a1 = ffma2(z2[1], wA.y, a1);
            a0 = ffma2(z2[2], wB.x, a0); a1 = ffma2(z2[3], wB.y, a1);
            a0 = ffma2(z2[4], wC.x, a0); a1 = ffma2(z2[5], wC.y, a1);
            a0 = ffma2(z2[6], wD.x, a0); a1 = ffma2(z2[7], wD.y, a1);
            float l0, h0f, l1, h1f;
            unpack2(a0, l0, h0f); unpack2(a1, l1, h1f);
            tmp[qo] = sbi[o] + ((l0 + h0f) + (l1 + h1f));
        }
        *(float4*)(dst + g3 * 4) = make_float4(tmp[0], tmp[1], tmp[2], tmp[3]);
    }
}

// ============================================================================
// K4: mixer GRU (2 layers, H=16), one warp per batch, split accumulator
// chains, exact activations (precision-critical).
// ============================================================================
__global__ void __launch_bounds__(32) k_mixer(
    const float* __restrict__ Whh0, const float* __restrict__ bhh0,
    const float* __restrict__ Wih1, const float* __restrict__ bih1,
    const float* __restrict__ Whh1, const float* __restrict__ bhh1)
{
    const int lane = threadIdx.x;
    const int b    = blockIdx.x;
    const bool hasB = (lane < 16);
    const int gA = lane, gB = 32 + lane;

    float uA0[16], uB0[16], wiA[16], wiB[16], uA1[16], uB1[16];
#pragma unroll
    for (int k = 0; k < 16; k++) {
        uA0[k] = Whh0[gA * 16 + k];
        wiA[k] = Wih1[gA * 16 + k];
        uA1[k] = Whh1[gA * 16 + k];
        uB0[k] = hasB ? Whh0[gB * 16 + k] : 0.f;
        wiB[k] = hasB ? Wih1[gB * 16 + k] : 0.f;
        uB1[k] = hasB ? Whh1[gB * 16 + k] : 0.f;
    }
    float bhA0 = bhh0[gA], bhB0 = hasB ? bhh0[gB] : 0.f;
    float biA1 = bih1[gA], biB1 = hasB ? bih1[gB] : 0.f;
    float bhA1 = bhh1[gA], bhB1 = hasB ? bhh1[gB] : 0.f;

    float h0 = 0.f, h1 = 0.f;
    const float* xp = g_xw0 + (size_t)b * Wn * 48;
    float xA = xp[lane];
    float xB = hasB ? xp[32 + lane] : 0.f;

    for (int t = 0; t < Wn; t++) {
        float cxA = xA, cxB = xB;
        if (t + 1 < Wn) {
            xA = xp[(size_t)(t + 1) * 48 + lane];
            xB = hasB ? xp[(size_t)(t + 1) * 48 + 32 + lane] : 0.f;
        }
        // layer 0 — two split chains per dot
        float dAa = bhA0, dAb = 0.f, dBa = bhB0, dBb = 0.f;
#pragma unroll
        for (int k = 0; k < 8; k++) {
            float hk = __shfl_sync(FULLMASK, h0, k);
            dAa = fmaf(uA0[k], hk, dAa);
            dBa = fmaf(uB0[k], hk, dBa);
        }
#pragma unroll
        for (int k = 8; k < 16; k++) {
            float hk = __shfl_sync(FULLMASK, h0, k);
            dAb = fmaf(uA0[k], hk, dAb);
            dBb = fmaf(uB0[k], hk, dBb);
        }
        float dA = dAa + dAb, dB = dBa + dBb;
        float s  = sigm_x(cxA + dA);
        float nv = tanh_x(fmaf(s, dB, cxB));
        float zz = __shfl_sync(FULLMASK, s, 16 + (lane & 15));
        float h0n = fmaf(zz, h0 - nv, nv);
        h0 = hasB ? h0n : h0;
        // layer 1
        float xAa = biA1, xAb = 0.f, xBa = biB1, xBb = 0.f;
        float dA1a = bhA1, dA1b = 0.f, dB1a = bhB1, dB1b = 0.f;
#pragma unroll
        for (int k = 0; k < 8; k++) {
            float hk  = __shfl_sync(FULLMASK, h0, k);
            xAa = fmaf(wiA[k], hk, xAa);
            xBa = fmaf(wiB[k], hk, xBa);
            float hk1 = __shfl_sync(FULLMASK, h1, k);
            dA1a = fmaf(uA1[k], hk1, dA1a);
            dB1a = fmaf(uB1[k], hk1, dB1a);
        }
#pragma unroll
        for (int k = 8; k < 16; k++) {
            float hk  = __shfl_sync(FULLMASK, h0, k);
            xAb = fmaf(wiA[k], hk, xAb);
            xBb = fmaf(wiB[k], hk, xBb);
            float hk1 = __shfl_sync(FULLMASK, h1, k);
            dA1b = fmaf(uA1[k], hk1, dA1b);
            dB1b = fmaf(uB1[k], hk1, dB1b);
        }
        float xw1A = xAa + xAb, xw1B = xBa + xBb;
        float gh1A = dA1a + dA1b, gh1B = dB1a + dB1b;
        float s1  = sigm_x(xw1A + gh1A);
        float nv1 = tanh_x(fmaf(s1, gh1B, xw1B));
        float z1  = __shfl_sync(FULLMASK, s1, 16 + (lane & 15));
        float h1n = fmaf(z1, h1 - nv1, nv1);
        h1 = hasB ? h1n : h1;
    }
    if (lane < 16) g_h1fin[b * 16 + lane] = h1;
}

// ============================================================================
// K5a: decoder expert layer-1 + BN + elu (64 rows). One block.
// ============================================================================
__global__ void k_dec1(
    const float* __restrict__ Remote,
    const float* __restrict__ w1, const float* __restrict__ b1,
    const float* __restrict__ gg, const float* __restrict__ bt)
{
    __shared__ float sw1[2176], sb1[128], sh[1024], sstat[32], sgb[32];
    const int tid = threadIdx.x;
    for (int i = tid; i < 2176; i += 1024) sw1[i] = w1[i];
    if (tid < 128) sb1[tid] = b1[tid];
    if (tid < 16) { sgb[tid] = gg[tid]; sgb[16 + tid] = bt[tid]; }
    __syncthreads();

    const int b = tid >> 4, hh = tid & 15;
    {
        float d[17];
#pragma unroll
        for (int k = 0; k < 16; k++) d[k] = g_h1fin[b * 16 + k];
        d[16] = Remote[((size_t)b * Wn + (Wn - 1)) * Fn + (An + TGTn)];
        float acc = 0.f;
#pragma unroll 1
        for (int e = 0; e < 8; e++) {
            float ro = g_Ro[((size_t)b * Wn + (Wn - 1)) * En + e];
            float pe = sb1[e * 16 + hh];
#pragma unroll
            for (int i = 0; i < 17; i++) pe = fmaf(d[i], sw1[e * 272 + i * 16 + hh], pe);
            acc = fmaf(ro, pe, acc);
        }
        sh[tid] = acc;
    }
    __syncthreads();
    if (tid < 16) {
        float s = 0.f, q = 0.f;
        for (int bb = 0; bb < 64; bb++) {
            float v = sh[bb * 16 + tid];
            s += v; q = fmaf(v, v, q);
        }
        float mean = s * (1.0f / 64.0f);
        float var  = q * (1.0f / 64.0f) - mean * mean;
        sstat[tid] = mean;
        sstat[16 + tid] = rsqrtf(var + 1e-5f);
    }
    __syncthreads();
    {
        float v = sh[tid];
        v = fmaf(sgb[hh] * (v - sstat[hh]), sstat[16 + hh], sgb[16 + hh]);
        g_dech[tid] = (v > 0.f) ? v : (__expf(v) - 1.0f);
    }
}

// ============================================================================
// K5b: decoder layer-2 -> out (64 x 128). 16 blocks x 512 threads.
// ============================================================================
#define DEC2_SMEM_BYTES ((16384 + 1024) * 4)
__global__ void __launch_bounds__(512) k_dec2(
    const float* __restrict__ w2, const float* __restrict__ b2,
    float* __restrict__ out)
{
    extern __shared__ float sm[];
    float* sw2 = sm;
    float* sb2 = sm + 16384;
    const int tid = threadIdx.x;
    {
        const float4* w24 = (const float4*)w2;
        float4* sw24 = (float4*)sw2;
        for (int i = tid; i < 4096; i += 512) sw24[i] = w24[i];
        for (int i = tid; i < 1024; i += 512) sb2[i] = b2[i];
    }
    __syncthreads();

    const int b = blockIdx.x * 4 + (tid >> 7);
    const int o = tid & 127;

    float dh[16];
    const float4* hp = (const float4*)(g_dech + b * 16);
#pragma unroll
    for (int q4 = 0; q4 < 4; q4++) {
        float4 v = hp[q4];
        dh[q4*4+0]=v.x; dh[q4*4+1]=v.y; dh[q4*4+2]=v.z; dh[q4*4+3]=v.w;
    }
    float ro[8];
#pragma unroll
    for (int e = 0; e < 8; e++) ro[e] = g_Ro[((size_t)b * Wn + (Wn - 1)) * En + e];

    float acc = 0.f;
#pragma unroll 1
    for (int e = 0; e < 8; e++) {
        float pe = sb2[e * 128 + o];
        const float* wrow = sw2 + e * 2048 + o;
#pragma unroll
        for (int h = 0; h < 16; h++) pe = fmaf(dh[h], wrow[h * 128], pe);
        acc = fmaf(ro[e], pe, acc);
    }
    out[b * 128 + o] = acc;
}

// ============================================================================
// Host launcher
// ============================================================================
extern "C" void kernel_launch(void* const* d_in, const int* in_sizes, int n_in,
                              void* d_out, int out_size)
{
    (void)n_in; (void)out_size;
    const float* P[30];
    for (int i = 0; i < 30; i++) P[i] = (const float*)d_in[i];

    const float *Local = P[0], *Remote = P[1];
    const float *gWih0 = P[2], *gWhh0 = P[3], *gbih0 = P[4], *gbhh0 = P[5];
    const float *gWih1 = P[6], *gWhh1 = P[7], *gbih1 = P[8], *gbhh1 = P[9];
    const float *aew1, *aeb1, *aew2, *aeb2, *aeg, *aebt;
    const float *mdw1, *mdb1, *mdw2, *mdb2, *mdg, *mdbt;
    const float *mWih0, *mWhh0, *mbih0, *mbhh0, *mWih1, *mWhh1, *mbih1, *mbhh1;

    if (in_sizes[10] == 16384) {   // reference-signature order
        aew1 = P[10]; aeb1 = P[11]; aew2 = P[12]; aeb2 = P[13]; aeg = P[14]; aebt = P[15];
        mdw1 = P[16]; mdb1 = P[17]; mdw2 = P[18]; mdb2 = P[19]; mdg = P[20]; mdbt = P[21];
        mWih0 = P[22]; mWhh0 = P[23]; mbih0 = P[24]; mbhh0 = P[25];
        mWih1 = P[26]; mWhh1 = P[27]; mbih1 = P[28]; mbhh1 = P[29];
    } else {                        // setup_inputs dict order
        mWih0 = P[10]; mWhh0 = P[11]; mbih0 = P[12]; mbhh0 = P[13];
        mWih1 = P[14]; mWhh1 = P[15]; mbih1 = P[16]; mbhh1 = P[17];
        aew1 = P[18]; aeb1 = P[19]; aew2 = P[20]; aeb2 = P[21]; aeg = P[22]; aebt = P[23];
        mdw1 = P[24]; mdb1 = P[25]; mdw2 = P[26]; mdb2 = P[27]; mdg = P[28]; mdbt = P[29];
    }

    cudaFuncSetAttribute(k_exp1, cudaFuncAttributeMaxDynamicSharedMemorySize, K2_SMEM_BYTES);
    cudaFuncSetAttribute(k_dec2, cudaFuncAttributeMaxDynamicSharedMemorySize, DEC2_SMEM_BYTES);

    k_gate<<<128, 32>>>(Local, Remote, gWih0, gWhh0, gbih0, gbhh0,
                        gWih1, gWhh1, gbih1, gbhh1);
    k_exp1<<<256, 256, K2_SMEM_BYTES>>>(Local, Remote, aew1, aeb1);
    k_bnstat<<<32, 256>>>();
    k_exp2<<<128, 256>>>(aew2, aeb2, aeg, aebt, mWih0, mbih0);
    k_mixer<<<64, 32>>>(mWhh0, mbhh0, mWih1, mbih1, mWhh1, mbhh1);
    k_dec1<<<1, 1024>>>(Remote, mdw1, mdb1, mdg, mdbt);
    k_dec2<<<16, 512, DEC2_SMEM_BYTES>>>(mdw2, mdb2, (float*)d_out);
}

// round 5
// speedup vs baseline: 1.2054x; 1.2054x over previous
#include <cuda_runtime.h>
#include <math.h>

#define FULLMASK 0xffffffffu
#define Bn   64
#define Wn   128
#define Fn   132
#define An   128
#define TGTn 3
#define En   8
#define HIDn 16
#define OUTn 128
#define NROW (Bn*Wn)

typedef unsigned long long u64;

// ---------------- scratch (device globals; no allocation) ----------------
__device__ float g_Lo[NROW*En];
__device__ float g_Ro[NROW*En];
__device__ float g_hL[NROW*HIDn];
__device__ float g_hR[NROW*HIDn];
__device__ float g_bn[2][2][HIDn];
__device__ float g_xw0[NROW*48];
__device__ float g_h1fin[Bn*HIDn];
__device__ float g_dech[Bn*HIDn];

// exact activations (mixer — precision-critical path)
__device__ __forceinline__ float sigm_x(float x) { return 1.0f / (1.0f + __expf(-x)); }
__device__ __forceinline__ float tanh_x(float x) { return fmaf(2.0f, sigm_x(2.0f * x), -1.0f); }
// HW-approx activations (gate — smoothed by softmax downstream)
__device__ __forceinline__ float tanh_a(float x) {
    float y; asm("tanh.approx.f32 %0, %1;" : "=f"(y) : "f"(x)); return y;
}
__device__ __forceinline__ float sigm_a(float x) { return fmaf(0.5f, tanh_a(0.5f * x), 0.5f); }

// packed f32x2 helpers
__device__ __forceinline__ u64 pack2(float lo, float hi) {
    u64 r; asm("mov.b64 %0, {%1,%2};" : "=l"(r) : "f"(lo), "f"(hi)); return r;
}
__device__ __forceinline__ void unpack2(u64 v, float& lo, float& hi) {
    asm("mov.b64 {%0,%1}, %2;" : "=f"(lo), "=f"(hi) : "l"(v));
}
__device__ __forceinline__ u64 ffma2(u64 a, u64 b, u64 c) {
    u64 d; asm("fma.rn.f32x2 %0, %1, %2, %3;" : "=l"(d) : "l"(a), "l"(b), "l"(c)); return d;
}

// ============================================================================
// K1: gate GRU (2 layers, H=8) + softmax. One warp per (side,batch).
// ============================================================================
__global__ void __launch_bounds__(32) k_gate(
    const float* __restrict__ Local, const float* __restrict__ Remote,
    const float* __restrict__ Wih0, const float* __restrict__ Whh0,
    const float* __restrict__ bih0, const float* __restrict__ bhh0,
    const float* __restrict__ Wih1, const float* __restrict__ Whh1,
    const float* __restrict__ bih1, const float* __restrict__ bhh1)
{
    const int lane = threadIdx.x;
    const int side = blockIdx.x >> 6;
    const int b    = blockIdx.x & 63;
    const float* in  = side ? Remote : Local;
    float*       out = side ? g_Ro   : g_Lo;

    float wa=0.f, wb=0.f, wc=0.f, bi0=0.f, bh0=0.f, bi1=0.f, bh1=0.f;
    float u0[8], wi1[8], u1[8];
#pragma unroll
    for (int k = 0; k < 8; k++) { u0[k]=0.f; wi1[k]=0.f; u1[k]=0.f; }
    if (lane < 24) {
        wa = Wih0[lane*3+0]; wb = Wih0[lane*3+1]; wc = Wih0[lane*3+2];
        bi0 = bih0[lane]; bh0 = bhh0[lane];
        bi1 = bih1[lane]; bh1 = bhh1[lane];
#pragma unroll
        for (int k = 0; k < 8; k++) {
            u0[k]  = Whh0[lane*8+k];
            wi1[k] = Wih1[lane*8+k];
            u1[k]  = Whh1[lane*8+k];
        }
    }

    float h0[8], h1[8];
#pragma unroll
    for (int j = 0; j < 8; j++) { h0[j]=0.f; h1[j]=0.f; }

    const float* px = in + (size_t)b * Wn * Fn + An;
    float x0 = px[0], x1 = px[1], x2 = px[2];

    for (int t = 0; t < Wn; t++) {
        float cx0 = x0, cx1 = x1, cx2 = x2;
        if (t + 1 < Wn) {
            const float* pn = px + (size_t)(t + 1) * Fn;
            x0 = pn[0]; x1 = pn[1]; x2 = pn[2];
        }
        // layer 0 (split 2-chain dot)
        float xw = fmaf(wa, cx0, fmaf(wb, cx1, fmaf(wc, cx2, bi0)));
        float ga = fmaf(u0[0],h0[0], fmaf(u0[2],h0[2], fmaf(u0[4],h0[4], fmaf(u0[6],h0[6], bh0))));
        float gb = fmaf(u0[1],h0[1], fmaf(u0[3],h0[3], fmaf(u0[5],h0[5], u0[7]*h0[7])));
        float gh = ga + gb;
        float s  = sigm_a(xw + gh);
        float r  = __shfl_sync(FULLMASK, s, lane & 7);
        float nv = tanh_a(fmaf(r, gh, xw));
#pragma unroll
        for (int j = 0; j < 8; j++) {
            float z = __shfl_sync(FULLMASK, s,  8 + j);
            float n = __shfl_sync(FULLMASK, nv, 16 + j);
            h0[j] = fmaf(z, h0[j] - n, n);
        }
        // layer 1
        float xa = fmaf(wi1[0],h0[0], fmaf(wi1[2],h0[2], fmaf(wi1[4],h0[4], fmaf(wi1[6],h0[6], bi1))));
        float xb = fmaf(wi1[1],h0[1], fmaf(wi1[3],h0[3], fmaf(wi1[5],h0[5], wi1[7]*h0[7])));
        float xw1 = xa + xb;
        float g1a = fmaf(u1[0],h1[0], fmaf(u1[2],h1[2], fmaf(u1[4],h1[4], fmaf(u1[6],h1[6], bh1))));
        float g1b = fmaf(u1[1],h1[1], fmaf(u1[3],h1[3], fmaf(u1[5],h1[5], u1[7]*h1[7])));
        float gh1 = g1a + g1b;
        float s1  = sigm_a(xw1 + gh1);
        float r1  = __shfl_sync(FULLMASK, s1, lane & 7);
        float nv1 = tanh_a(fmaf(r1, gh1, xw1));
#pragma unroll
        for (int j = 0; j < 8; j++) {
            float z = __shfl_sync(FULLMASK, s1,  8 + j);
            float n = __shfl_sync(FULLMASK, nv1, 16 + j);
            h1[j] = fmaf(z, h1[j] - n, n);
        }
        // softmax over replicated h1 (|h1|<1 -> no max-subtraction needed)
        float ex[8];
#pragma unroll
        for (int j = 0; j < 8; j++) ex[j] = __expf(h1[j]);
        float sA = (ex[0]+ex[1]) + (ex[2]+ex[3]);
        float sB = (ex[4]+ex[5]) + (ex[6]+ex[7]);
        float inv = __frcp_rn(sA + sB);
        if (lane < 8) {
            float v = ex[0];
#pragma unroll
            for (int j = 1; j < 8; j++) if (lane == j) v = ex[j];
            out[((size_t)b * Wn + t) * En + lane] = v * inv;
        }
    }
}

// ============================================================================
// K2: expert layer-1 with f32x2 FFMA. 256 blocks (side x 128 tiles of 64 rows).
// ============================================================================
#define K2_SMEM_BYTES ((16384 + 64*129 + 512 + 128) * 4)
__global__ void __launch_bounds__(256) k_exp1(
    const float* __restrict__ Local, const float* __restrict__ Remote,
    const float* __restrict__ w1, const float* __restrict__ b1)
{
    extern __shared__ float sm[];
    float* sw1 = sm;
    float* sx  = sw1 + 16384;
    float* som = sx + 64 * 129;
    float* sb1 = som + 512;

    const int tid  = threadIdx.x;
    const int side = blockIdx.x >> 7;
    const int tile = blockIdx.x & 127;
    const int n0   = tile * 64;
    const float* in  = side ? Remote : Local;
    const float* om  = side ? g_Ro   : g_Lo;
    float*       dst = side ? g_hR   : g_hL;

    {
        const float4* w14 = (const float4*)w1;
        float4* sw14 = (float4*)sw1;
        for (int i = tid; i < 4096; i += 256) sw14[i] = w14[i];
        for (int i = tid; i < 64 * 128; i += 256) {
            int r = i >> 7, c = i & 127;
            sx[r * 129 + c] = in[(size_t)(n0 + r) * Fn + c];
        }
        for (int i = tid; i < 512; i += 256) som[i] = om[(size_t)n0 * En + i];
        if (tid < 128) sb1[tid] = b1[tid];
    }
    __syncthreads();

    const int r = tid >> 2;
    const int q = tid & 3;
    const float* xrow = sx + r * 129;

    u64 acc0 = pack2(0.f, 0.f), acc1 = pack2(0.f, 0.f);

#pragma unroll 1
    for (int e = 0; e < 8; e++) {
        u64 p0 = pack2(sb1[e*16 + q*4 + 0], sb1[e*16 + q*4 + 1]);
        u64 p1 = pack2(sb1[e*16 + q*4 + 2], sb1[e*16 + q*4 + 3]);
        const ulonglong2* wq = (const ulonglong2*)(sw1 + e * 2048) + q;
#pragma unroll 4
        for (int i = 0; i < 128; i++) {
            float xv = xrow[i];
            u64 x2 = pack2(xv, xv);
            ulonglong2 w = wq[i * 4];
            p0 = ffma2(x2, w.x, p0);
            p1 = ffma2(x2, w.y, p1);
        }
        float oe = som[r * 8 + e];
        u64 o2 = pack2(oe, oe);
        acc0 = ffma2(o2, p0, acc0);
        acc1 = ffma2(o2, p1, acc1);
    }
    ulonglong2 outv; outv.x = acc0; outv.y = acc1;
    *(ulonglong2*)(dst + (size_t)(n0 + r) * 16 + q * 4) = outv;
}

// ============================================================================
// K2b: deterministic BN statistics. 32 blocks = (side,h), 256 threads.
// ============================================================================
__global__ void k_bnstat()
{
    __shared__ float ss[256], sq[256];
    const int side = blockIdx.x >> 4, h = blockIdx.x & 15, tid = threadIdx.x;
    const float* src = side ? g_hR : g_hL;
    float s = 0.f, q = 0.f;
    for (int r = tid; r < NROW; r += 256) {
        float v = src[(size_t)r * 16 + h];
        s += v; q = fmaf(v, v, q);
    }
    ss[tid] = s; sq[tid] = q;
    __syncthreads();
    for (int ofs = 128; ofs > 0; ofs >>= 1) {
        if (tid < ofs) { ss[tid] += ss[tid + ofs]; sq[tid] += sq[tid + ofs]; }
        __syncthreads();
    }
    if (tid == 0) { g_bn[side][0][h] = ss[0]; g_bn[side][1][h] = sq[0]; }
}

// ============================================================================
// K3 (v3): expert layer-2 as dense GEMM.
//   u[n, e*16+h] = omL[n,e]*elu(bnL(hL[n,h])) + omR[n,e]*elu(bnR(hR[n,h]))
//   z[n,o] = u[n,:] @ W2flat[:,o] + (omL+omR)[n,:] @ b2[:,o]
//   xw0[n,:48] = z[n,:] @ Wih0m^T + bih0m
// Block = 64 rows, 256 threads, 3 phases.
// ============================================================================
#define EXP2_SMEM_FLOATS (16*132 + 128 + 768 + 48 + 16 + 16 + 64 + 64*136 + 64*20)
#define EXP2_SMEM_BYTES  (EXP2_SMEM_FLOATS * 4)
__global__ void __launch_bounds__(256) k_exp2(
    const float* __restrict__ w2, const float* __restrict__ b2,
    const float* __restrict__ aeg, const float* __restrict__ aebt,
    const float* __restrict__ Wih0m, const float* __restrict__ bih0m)
{
    extern __shared__ float sm[];
    float* sW2T  = sm;                 // [o][i] 16 x 132 (transposed W2flat)
    float* sb2   = sW2T + 16*132;      // 128 (E,16)
    float* sWp   = sb2 + 128;          // 768 (48,16)
    float* sbi   = sWp + 768;          // 48
    float* sg    = sbi + 48;           // 16
    float* sbt   = sg + 16;            // 16
    float* sstat = sbt + 16;           // [side][m/inv][16] = 64
    float* su    = sstat + 64;         // 64 x 136 (cols 128..135 = omL+omR)
    float* sz    = su + 64*136;        // 64 x 20

    const int tid = threadIdx.x;
    for (int i = tid; i < 2048; i += 256) {
        int ii = i >> 4, o = i & 15;
        sW2T[o * 132 + ii] = w2[i];
    }
    for (int i = tid; i < 768; i += 256) sWp[i] = Wih0m[i];
    if (tid < 128) sb2[tid] = b2[tid];
    if (tid < 48)  sbi[tid] = bih0m[tid];
    if (tid < 16)  { sg[tid] = aeg[tid]; sbt[tid] = aebt[tid]; }
    if (tid < 32) {
        int side = tid >> 4, h = tid & 15;
        float mean = g_bn[side][0][h] * (1.0f / NROW);
        float var  = g_bn[side][1][h] * (1.0f / NROW) - mean * mean;
        sstat[side * 32 + h]      = mean;
        sstat[side * 32 + 16 + h] = rsqrtf(var + 1e-5f);
    }
    __syncthreads();

    const int r = tid >> 2;          // 0..63
    const int q = tid & 3;           // h-quad / output-slice
    const int n = blockIdx.x * 64 + r;

    {   // ---- phase A: build u ----
        float4 hl4 = *(const float4*)(g_hL + (size_t)n * 16 + q * 4);
        float4 hr4 = *(const float4*)(g_hR + (size_t)n * 16 + q * 4);
        float hL[4] = {hl4.x, hl4.y, hl4.z, hl4.w};
        float hR[4] = {hr4.x, hr4.y, hr4.z, hr4.w};
#pragma unroll
        for (int j = 0; j < 4; j++) {
            int h = q * 4 + j;
            float vL = fmaf(sg[h] * (hL[j] - sstat[h]),      sstat[16 + h],  sbt[h]);
            float vR = fmaf(sg[h] * (hR[j] - sstat[32 + h]), sstat[48 + h], sbt[h]);
            hL[j] = (vL > 0.f) ? vL : (__expf(vL) - 1.0f);
            hR[j] = (vR > 0.f) ? vR : (__expf(vR) - 1.0f);
        }
        float oL[8], oR[8];
#pragma unroll
        for (int e = 0; e < 8; e++) {
            oL[e] = g_Lo[(size_t)n * 8 + e];
            oR[e] = g_Ro[(size_t)n * 8 + e];
        }
        float* ur = su + r * 136;
#pragma unroll
        for (int e = 0; e < 8; e++) {
#pragma unroll
            for (int j = 0; j < 4; j++)
                ur[e * 16 + q * 4 + j] = fmaf(oL[e], hL[j], oR[e] * hR[j]);
        }
        if (q == 0) {
#pragma unroll
            for (int e = 0; e < 8; e++) ur[128 + e] = oL[e] + oR[e];
        }
    }
    __syncthreads();

    {   // ---- phase B: z = u @ W2flat + omsum @ b2 ; thread=(4-row grp, o) ----
        const int g4 = tid >> 4;     // 0..15
        const int o  = tid & 15;
        const int r0 = g4 * 4;
        float acc[4];
#pragma unroll
        for (int j = 0; j < 4; j++) {
            float a = 0.f;
            const float* os = su + (r0 + j) * 136 + 128;
#pragma unroll
            for (int e = 0; e < 8; e++) a = fmaf(os[e], sb2[e * 16 + o], a);
            acc[j] = a;
        }
        const float* wrow = sW2T + o * 132;
#pragma unroll 4
        for (int i = 0; i < 128; i += 4) {
            float4 w = *(const float4*)(wrow + i);
#pragma unroll
            for (int j = 0; j < 4; j++) {
                float4 u = *(const float4*)(su + (r0 + j) * 136 + i);
                acc[j] = fmaf(u.x, w.x, acc[j]);
                acc[j] = fmaf(u.y, w.y, acc[j]);
                acc[j] = fmaf(u.z, w.z, acc[j]);
                acc[j] = fmaf(u.w, w.w, acc[j]);
            }
        }
#pragma unroll
        for (int j = 0; j < 4; j++) sz[(r0 + j) * 20 + o] = acc[j];
    }
    __syncthreads();

    {   // ---- phase C: xw0 = z @ Wp^T + b ; thread=(r, 12-output slice) ----
        float zv[16];
        const float4* zp = (const float4*)(sz + r * 20);
#pragma unroll
        for (int q4 = 0; q4 < 4; q4++) {
            float4 v = zp[q4];
            zv[q4*4+0]=v.x; zv[q4*4+1]=v.y; zv[q4*4+2]=v.z; zv[q4*4+3]=v.w;
        }
        float* dst = g_xw0 + (size_t)n * 48 + q * 12;
#pragma unroll
        for (int g3 = 0; g3 < 3; g3++) {
            float tmp[4];
#pragma unroll
            for (int jo = 0; jo < 4; jo++) {
                int o = q * 12 + g3 * 4 + jo;
                const float* wr = sWp + o * 16;
                float a = sbi[o], b2a = 0.f;
#pragma unroll
                for (int k = 0; k < 16; k += 2) {
                    a   = fmaf(zv[k],   wr[k],   a);
                    b2a = fmaf(zv[k+1], wr[k+1], b2a);
                }
                tmp[jo] = a + b2a;
            }
            *(float4*)(dst + g3 * 4) = make_float4(tmp[0], tmp[1], tmp[2], tmp[3]);
        }
    }
}

// ============================================================================
// K4: mixer GRU (2 layers, H=16), one warp per batch, exact activations.
// ============================================================================
__global__ void __launch_bounds__(32) k_mixer(
    const float* __restrict__ Whh0, const float* __restrict__ bhh0,
    const float* __restrict__ Wih1, const float* __restrict__ bih1,
    const float* __restrict__ Whh1, const float* __restrict__ bhh1)
{
    const int lane = threadIdx.x;
    const int b    = blockIdx.x;
    const bool hasB = (lane < 16);
    const int gA = lane, gB = 32 + lane;

    float uA0[16], uB0[16], wiA[16], wiB[16], uA1[16], uB1[16];
#pragma unroll
    for (int k = 0; k < 16; k++) {
        uA0[k] = Whh0[gA * 16 + k];
        wiA[k] = Wih1[gA * 16 + k];
        uA1[k] = Whh1[gA * 16 + k];
        uB0[k] = hasB ? Whh0[gB * 16 + k] : 0.f;
        wiB[k] = hasB ? Wih1[gB * 16 + k] : 0.f;
        uB1[k] = hasB ? Whh1[gB * 16 + k] : 0.f;
    }
    float bhA0 = bhh0[gA], bhB0 = hasB ? bhh0[gB] : 0.f;
    float biA1 = bih1[gA], biB1 = hasB ? bih1[gB] : 0.f;
    float bhA1 = bhh1[gA], bhB1 = hasB ? bhh1[gB] : 0.f;

    float h0 = 0.f, h1 = 0.f;
    const float* xp = g_xw0 + (size_t)b * Wn * 48;
    float xA = xp[lane];
    float xB = hasB ? xp[32 + lane] : 0.f;

    for (int t = 0; t < Wn; t++) {
        float cxA = xA, cxB = xB;
        if (t + 1 < Wn) {
            xA = xp[(size_t)(t + 1) * 48 + lane];
            xB = hasB ? xp[(size_t)(t + 1) * 48 + 32 + lane] : 0.f;
        }
        float dAa = bhA0, dAb = 0.f, dBa = bhB0, dBb = 0.f;
#pragma unroll
        for (int k = 0; k < 8; k++) {
            float hk = __shfl_sync(FULLMASK, h0, k);
            dAa = fmaf(uA0[k], hk, dAa);
            dBa = fmaf(uB0[k], hk, dBa);
        }
#pragma unroll
        for (int k = 8; k < 16; k++) {
            float hk = __shfl_sync(FULLMASK, h0, k);
            dAb = fmaf(uA0[k], hk, dAb);
            dBb = fmaf(uB0[k], hk, dBb);
        }
        float dA = dAa + dAb, dB = dBa + dBb;
        float s  = sigm_x(cxA + dA);
        float nv = tanh_x(fmaf(s, dB, cxB));
        float zz = __shfl_sync(FULLMASK, s, 16 + (lane & 15));
        float h0n = fmaf(zz, h0 - nv, nv);
        h0 = hasB ? h0n : h0;

        float xAa = biA1, xAb = 0.f, xBa = biB1, xBb = 0.f;
        float dA1a = bhA1, dA1b = 0.f, dB1a = bhB1, dB1b = 0.f;
#pragma unroll
        for (int k = 0; k < 8; k++) {
            float hk  = __shfl_sync(FULLMASK, h0, k);
            xAa = fmaf(wiA[k], hk, xAa);
            xBa = fmaf(wiB[k], hk, xBa);
            float hk1 = __shfl_sync(FULLMASK, h1, k);
            dA1a = fmaf(uA1[k], hk1, dA1a);
            dB1a = fmaf(uB1[k], hk1, dB1a);
        }
#pragma unroll
        for (int k = 8; k < 16; k++) {
            float hk  = __shfl_sync(FULLMASK, h0, k);
            xAb = fmaf(wiA[k], hk, xAb);
            xBb = fmaf(wiB[k], hk, xBb);
            float hk1 = __shfl_sync(FULLMASK, h1, k);
            dA1b = fmaf(uA1[k], hk1, dA1b);
            dB1b = fmaf(uB1[k], hk1, dB1b);
        }
        float xw1A = xAa + xAb, xw1B = xBa + xBb;
        float gh1A = dA1a + dA1b, gh1B = dB1a + dB1b;
        float s1  = sigm_x(xw1A + gh1A);
        float nv1 = tanh_x(fmaf(s1, gh1B, xw1B));
        float z1  = __shfl_sync(FULLMASK, s1, 16 + (lane & 15));
        float h1n = fmaf(z1, h1 - nv1, nv1);
        h1 = hasB ? h1n : h1;
    }
    if (lane < 16) g_h1fin[b * 16 + lane] = h1;
}

// ============================================================================
// K5a: decoder expert layer-1 + BN + elu (64 rows). One block.
// ============================================================================
__global__ void k_dec1(
    const float* __restrict__ Remote,
    const float* __restrict__ w1, const float* __restrict__ b1,
    const float* __restrict__ gg, const float* __restrict__ bt)
{
    __shared__ float sw1[2176], sb1[128], sh[1024], sstat[32], sgb[32];
    const int tid = threadIdx.x;
    for (int i = tid; i < 2176; i += 1024) sw1[i] = w1[i];
    if (tid < 128) sb1[tid] = b1[tid];
    if (tid < 16) { sgb[tid] = gg[tid]; sgb[16 + tid] = bt[tid]; }
    __syncthreads();

    const int b = tid >> 4, hh = tid & 15;
    {
        float d[17];
#pragma unroll
        for (int k = 0; k < 16; k++) d[k] = g_h1fin[b * 16 + k];
        d[16] = Remote[((size_t)b * Wn + (Wn - 1)) * Fn + (An + TGTn)];
        float acc = 0.f;
#pragma unroll 1
        for (int e = 0; e < 8; e++) {
            float ro = g_Ro[((size_t)b * Wn + (Wn - 1)) * En + e];
            float pe = sb1[e * 16 + hh];
#pragma unroll
            for (int i = 0; i < 17; i++) pe = fmaf(d[i], sw1[e * 272 + i * 16 + hh], pe);
            acc = fmaf(ro, pe, acc);
        }
        sh[tid] = acc;
    }
    __syncthreads();
    if (tid < 16) {
        float s = 0.f, q = 0.f;
        for (int bb = 0; bb < 64; bb++) {
            float v = sh[bb * 16 + tid];
            s += v; q = fmaf(v, v, q);
        }
        float mean = s * (1.0f / 64.0f);
        float var  = q * (1.0f / 64.0f) - mean * mean;
        sstat[tid] = mean;
        sstat[16 + tid] = rsqrtf(var + 1e-5f);
    }
    __syncthreads();
    {
        float v = sh[tid];
        v = fmaf(sgb[hh] * (v - sstat[hh]), sstat[16 + hh], sgb[16 + hh]);
        g_dech[tid] = (v > 0.f) ? v : (__expf(v) - 1.0f);
    }
}

// ============================================================================
// K5b: decoder layer-2 -> out (64 x 128). 16 blocks x 512 threads.
// ============================================================================
#define DEC2_SMEM_BYTES ((16384 + 1024) * 4)
__global__ void __launch_bounds__(512) k_dec2(
    const float* __restrict__ w2, const float* __restrict__ b2,
    float* __restrict__ out)
{
    extern __shared__ float sm[];
    float* sw2 = sm;
    float* sb2 = sm + 16384;
    const int tid = threadIdx.x;
    {
        const float4* w24 = (const float4*)w2;
        float4* sw24 = (float4*)sw2;
        for (int i = tid; i < 4096; i += 512) sw24[i] = w24[i];
        for (int i = tid; i < 1024; i += 512) sb2[i] = b2[i];
    }
    __syncthreads();

    const int b = blockIdx.x * 4 + (tid >> 7);
    const int o = tid & 127;

    float dh[16];
    const float4* hp = (const float4*)(g_dech + b * 16);
#pragma unroll
    for (int q4 = 0; q4 < 4; q4++) {
        float4 v = hp[q4];
        dh[q4*4+0]=v.x; dh[q4*4+1]=v.y; dh[q4*4+2]=v.z; dh[q4*4+3]=v.w;
    }
    float ro[8];
#pragma unroll
    for (int e = 0; e < 8; e++) ro[e] = g_Ro[((size_t)b * Wn + (Wn - 1)) * En + e];

    float acc = 0.f;
#pragma unroll 1
    for (int e = 0; e < 8; e++) {
        float pe = sb2[e * 128 + o];
        const float* wrow = sw2 + e * 2048 + o;
#pragma unroll
        for (int h = 0; h < 16; h++) pe = fmaf(dh[h], wrow[h * 128], pe);
        acc = fmaf(ro[e], pe, acc);
    }
    out[b * 128 + o] = acc;
}

// ============================================================================
// Host launcher
// ============================================================================
extern "C" void kernel_launch(void* const* d_in, const int* in_sizes, int n_in,
                              void* d_out, int out_size)
{
    (void)n_in; (void)out_size;
    const float* P[30];
    for (int i = 0; i < 30; i++) P[i] = (const float*)d_in[i];

    const float *Local = P[0], *Remote = P[1];
    const float *gWih0 = P[2], *gWhh0 = P[3], *gbih0 = P[4], *gbhh0 = P[5];
    const float *gWih1 = P[6], *gWhh1 = P[7], *gbih1 = P[8], *gbhh1 = P[9];
    const float *aew1, *aeb1, *aew2, *aeb2, *aeg, *aebt;
    const float *mdw1, *mdb1, *mdw2, *mdb2, *mdg, *mdbt;
    const float *mWih0, *mWhh0, *mbih0, *mbhh0, *mWih1, *mWhh1, *mbih1, *mbhh1;

    if (in_sizes[10] == 16384) {   // reference-signature order
        aew1 = P[10]; aeb1 = P[11]; aew2 = P[12]; aeb2 = P[13]; aeg = P[14]; aebt = P[15];
        mdw1 = P[16]; mdb1 = P[17]; mdw2 = P[18]; mdb2 = P[19]; mdg = P[20]; mdbt = P[21];
        mWih0 = P[22]; mWhh0 = P[23]; mbih0 = P[24]; mbhh0 = P[25];
        mWih1 = P[26]; mWhh1 = P[27]; mbih1 = P[28]; mbhh1 = P[29];
    } else {                        // setup_inputs dict order
        mWih0 = P[10]; mWhh0 = P[11]; mbih0 = P[12]; mbhh0 = P[13];
        mWih1 = P[14]; mWhh1 = P[15]; mbih1 = P[16]; mbhh1 = P[17];
        aew1 = P[18]; aeb1 = P[19]; aew2 = P[20]; aeb2 = P[21]; aeg = P[22]; aebt = P[23];
        mdw1 = P[24]; mdb1 = P[25]; mdw2 = P[26]; mdb2 = P[27]; mdg = P[28]; mdbt = P[29];
    }

    cudaFuncSetAttribute(k_exp1, cudaFuncAttributeMaxDynamicSharedMemorySize, K2_SMEM_BYTES);
    cudaFuncSetAttribute(k_exp2, cudaFuncAttributeMaxDynamicSharedMemorySize, EXP2_SMEM_BYTES);
    cudaFuncSetAttribute(k_dec2, cudaFuncAttributeMaxDynamicSharedMemorySize, DEC2_SMEM_BYTES);

    k_gate<<<128, 32>>>(Local, Remote, gWih0, gWhh0, gbih0, gbhh0,
                        gWih1, gWhh1, gbih1, gbhh1);
    k_exp1<<<256, 256, K2_SMEM_BYTES>>>(Local, Remote, aew1, aeb1);
    k_bnstat<<<32, 256>>>();
    k_exp2<<<128, 256, EXP2_SMEM_BYTES>>>(aew2, aeb2, aeg, aebt, mWih0, mbih0);
    k_mixer<<<64, 32>>>(mWhh0, mbhh0, mWih1, mbih1, mWhh1, mbhh1);
    k_dec1<<<1, 1024>>>(Remote, mdw1, mdb1, mdg, mdbt);
    k_dec2<<<16, 512, DEC2_SMEM_BYTES>>>(mdw2, mdb2, (float*)d_out);
}

// round 6
// speedup vs baseline: 1.3600x; 1.1282x over previous
#include <cuda_runtime.h>
#include <math.h>

#define FULLMASK 0xffffffffu
#define Bn   64
#define Wn   128
#define Fn   132
#define An   128
#define TGTn 3
#define En   8
#define HIDn 16
#define OUTn 128
#define NROW (Bn*Wn)

typedef unsigned long long u64;

// ---------------- scratch (device globals; no allocation) ----------------
__device__ float g_Lo[NROW*En];
__device__ float g_Ro[NROW*En];
__device__ float g_y[2*NROW*128];      // per-expert pre-activations, both sides
__device__ float g_hL[NROW*HIDn];
__device__ float g_hR[NROW*HIDn];
__device__ float g_part[2][32][2][16]; // per-chunk BN partials
__device__ float g_xw0[NROW*48];
__device__ float g_h1fin[Bn*HIDn];
__device__ float g_dech[Bn*HIDn];

// HW-approx activations
__device__ __forceinline__ float tanh_a(float x) {
    float y; asm("tanh.approx.f32 %0, %1;" : "=f"(y) : "f"(x)); return y;
}
__device__ __forceinline__ float sigm_a(float x) { return fmaf(0.5f, tanh_a(0.5f * x), 0.5f); }

// packed f32x2 helpers
__device__ __forceinline__ u64 pack2(float lo, float hi) {
    u64 r; asm("mov.b64 %0, {%1,%2};" : "=l"(r) : "f"(lo), "f"(hi)); return r;
}
__device__ __forceinline__ void unpack2(u64 v, float& lo, float& hi) {
    asm("mov.b64 {%0,%1}, %2;" : "=f"(lo), "=f"(hi) : "l"(v));
}
__device__ __forceinline__ u64 ffma2(u64 a, u64 b, u64 c) {
    u64 d; asm("fma.rn.f32x2 %0, %1, %2, %3;" : "=l"(d) : "l"(a), "l"(b), "l"(c)); return d;
}

// ============================================================================
// K1 fused: blocks 0..127 = gate GRU (1 warp per (side,batch));
//           blocks 128..383 = per-expert GEMM y = x @ w1 + b1 (no gate dep).
// ============================================================================
#define GE1_SMEM_BYTES ((64*129 + 128) * 4)
__global__ void __launch_bounds__(256) k_ge1(
    const float* __restrict__ Local, const float* __restrict__ Remote,
    const float* __restrict__ Wih0, const float* __restrict__ Whh0,
    const float* __restrict__ bih0, const float* __restrict__ bhh0,
    const float* __restrict__ Wih1, const float* __restrict__ Whh1,
    const float* __restrict__ bih1, const float* __restrict__ bhh1,
    const float* __restrict__ w1,   const float* __restrict__ b1)
{
    if (blockIdx.x < 128) {
        // ---------------- gate GRU path ----------------
        if (threadIdx.x >= 32) return;
        const int lane = threadIdx.x;
        const int side = blockIdx.x >> 6;
        const int b    = blockIdx.x & 63;
        const float* in  = side ? Remote : Local;
        float*       out = side ? g_Ro   : g_Lo;

        float wa=0.f, wb=0.f, wc=0.f, bi0=0.f, bh0=0.f, bi1=0.f, bh1=0.f;
        float u0[8], wi1[8], u1[8];
#pragma unroll
        for (int k = 0; k < 8; k++) { u0[k]=0.f; wi1[k]=0.f; u1[k]=0.f; }
        if (lane < 24) {
            wa = Wih0[lane*3+0]; wb = Wih0[lane*3+1]; wc = Wih0[lane*3+2];
            bi0 = bih0[lane]; bh0 = bhh0[lane];
            bi1 = bih1[lane]; bh1 = bhh1[lane];
#pragma unroll
            for (int k = 0; k < 8; k++) {
                u0[k]  = Whh0[lane*8+k];
                wi1[k] = Wih1[lane*8+k];
                u1[k]  = Whh1[lane*8+k];
            }
        }
        float h0[8], h1[8];
#pragma unroll
        for (int j = 0; j < 8; j++) { h0[j]=0.f; h1[j]=0.f; }

        const float* px = in + (size_t)b * Wn * Fn + An;
        float x0 = px[0], x1 = px[1], x2 = px[2];

        for (int t = 0; t < Wn; t++) {
            float cx0 = x0, cx1 = x1, cx2 = x2;
            if (t + 1 < Wn) {
                const float* pn = px + (size_t)(t + 1) * Fn;
                x0 = pn[0]; x1 = pn[1]; x2 = pn[2];
            }
            // layer 0
            float xw = fmaf(wa, cx0, fmaf(wb, cx1, fmaf(wc, cx2, bi0)));
            float ga = fmaf(u0[0],h0[0], fmaf(u0[2],h0[2], fmaf(u0[4],h0[4], fmaf(u0[6],h0[6], bh0))));
            float gb = fmaf(u0[1],h0[1], fmaf(u0[3],h0[3], fmaf(u0[5],h0[5], u0[7]*h0[7])));
            float gh = ga + gb;
            float s  = sigm_a(xw + gh);
            float r  = __shfl_sync(FULLMASK, s, lane & 7);
            float nv = tanh_a(fmaf(r, gh, xw));
#pragma unroll
            for (int j = 0; j < 8; j++) {
                float z = __shfl_sync(FULLMASK, s,  8 + j);
                float n = __shfl_sync(FULLMASK, nv, 16 + j);
                h0[j] = fmaf(z, h0[j] - n, n);
            }
            // layer 1
            float xa = fmaf(wi1[0],h0[0], fmaf(wi1[2],h0[2], fmaf(wi1[4],h0[4], fmaf(wi1[6],h0[6], bi1))));
            float xb = fmaf(wi1[1],h0[1], fmaf(wi1[3],h0[3], fmaf(wi1[5],h0[5], wi1[7]*h0[7])));
            float xw1 = xa + xb;
            float g1a = fmaf(u1[0],h1[0], fmaf(u1[2],h1[2], fmaf(u1[4],h1[4], fmaf(u1[6],h1[6], bh1))));
            float g1b = fmaf(u1[1],h1[1], fmaf(u1[3],h1[3], fmaf(u1[5],h1[5], u1[7]*h1[7])));
            float gh1 = g1a + g1b;
            float s1  = sigm_a(xw1 + gh1);
            float r1  = __shfl_sync(FULLMASK, s1, lane & 7);
            float nv1 = tanh_a(fmaf(r1, gh1, xw1));
#pragma unroll
            for (int j = 0; j < 8; j++) {
                float z = __shfl_sync(FULLMASK, s1,  8 + j);
                float n = __shfl_sync(FULLMASK, nv1, 16 + j);
                h1[j] = fmaf(z, h1[j] - n, n);
            }
            // softmax (|h1|<1, no max-subtract)
            float ex[8];
#pragma unroll
            for (int j = 0; j < 8; j++) ex[j] = __expf(h1[j]);
            float sA = (ex[0]+ex[1]) + (ex[2]+ex[3]);
            float sB = (ex[4]+ex[5]) + (ex[6]+ex[7]);
            float inv = __frcp_rn(sA + sB);
            if (lane < 8) {
                float v = ex[0];
#pragma unroll
                for (int j = 1; j < 8; j++) if (lane == j) v = ex[j];
                out[((size_t)b * Wn + t) * En + lane] = v * inv;
            }
        }
        return;
    }

    // ---------------- per-expert GEMM path ----------------
    extern __shared__ float sm[];
    float* sx  = sm;                 // 64 x 129
    float* sb1 = sx + 64 * 129;      // 128

    const int gid  = blockIdx.x - 128;
    const int side = gid >> 7;
    const int tile = gid & 127;
    const int n0   = tile * 64;
    const float* in = side ? Remote : Local;
    const int tid   = threadIdx.x;

    for (int i = tid; i < 64 * 128; i += 256) {
        int r = i >> 7, c = i & 127;
        sx[r * 129 + c] = in[(size_t)(n0 + r) * Fn + c];
    }
    if (tid < 128) sb1[tid] = b1[tid];
    __syncthreads();

    const int rg = tid >> 4, cg = tid & 15;
    const int r0 = rg * 4, c0 = cg * 8;
    const int e  = c0 >> 4, hb = c0 & 15;      // 8 cols live in one expert
    const float* wbase = w1 + e * 2048 + hb;   // + k*16 to step K

    u64 acc[4][4];
    {
        u64 i0 = pack2(sb1[c0+0], sb1[c0+1]);
        u64 i1 = pack2(sb1[c0+2], sb1[c0+3]);
        u64 i2 = pack2(sb1[c0+4], sb1[c0+5]);
        u64 i3 = pack2(sb1[c0+6], sb1[c0+7]);
#pragma unroll
        for (int j = 0; j < 4; j++) { acc[j][0]=i0; acc[j][1]=i1; acc[j][2]=i2; acc[j][3]=i3; }
    }

#pragma unroll 2
    for (int k = 0; k < 128; k++) {
        float xv0 = sx[(r0+0)*129 + k];
        float xv1 = sx[(r0+1)*129 + k];
        float xv2 = sx[(r0+2)*129 + k];
        float xv3 = sx[(r0+3)*129 + k];
        ulonglong2 wA = *(const ulonglong2*)(wbase + k*16);
        ulonglong2 wB = *(const ulonglong2*)(wbase + k*16 + 4);
        u64 x0 = pack2(xv0, xv0), x1 = pack2(xv1, xv1);
        u64 x2 = pack2(xv2, xv2), x3 = pack2(xv3, xv3);
        acc[0][0]=ffma2(x0,wA.x,acc[0][0]); acc[0][1]=ffma2(x0,wA.y,acc[0][1]);
        acc[0][2]=ffma2(x0,wB.x,acc[0][2]); acc[0][3]=ffma2(x0,wB.y,acc[0][3]);
        acc[1][0]=ffma2(x1,wA.x,acc[1][0]); acc[1][1]=ffma2(x1,wA.y,acc[1][1]);
        acc[1][2]=ffma2(x1,wB.x,acc[1][2]); acc[1][3]=ffma2(x1,wB.y,acc[1][3]);
        acc[2][0]=ffma2(x2,wA.x,acc[2][0]); acc[2][1]=ffma2(x2,wA.y,acc[2][1]);
        acc[2][2]=ffma2(x2,wB.x,acc[2][2]); acc[2][3]=ffma2(x2,wB.y,acc[2][3]);
        acc[3][0]=ffma2(x3,wA.x,acc[3][0]); acc[3][1]=ffma2(x3,wA.y,acc[3][1]);
        acc[3][2]=ffma2(x3,wB.x,acc[3][2]); acc[3][3]=ffma2(x3,wB.y,acc[3][3]);
    }

#pragma unroll
    for (int j = 0; j < 4; j++) {
        float* yrow = g_y + ((size_t)side * NROW + n0 + r0 + j) * 128 + c0;
        ulonglong2 v0; v0.x = acc[j][0]; v0.y = acc[j][1];
        ulonglong2 v1; v1.x = acc[j][2]; v1.y = acc[j][3];
        *(ulonglong2*)(yrow)     = v0;
        *(ulonglong2*)(yrow + 4) = v1;
    }
}

// ============================================================================
// K2: combine h = sum_e om*y, plus deterministic per-block BN partials.
// grid 64 = (side, chunk of 256 rows); 256 threads = 1 row each.
// ============================================================================
__global__ void __launch_bounds__(256) k_comb()
{
    __shared__ float ssum[16][256];
    __shared__ float ssq [16][256];

    const int tid   = threadIdx.x;
    const int side  = blockIdx.x >> 5;
    const int chunk = blockIdx.x & 31;
    const int n     = chunk * 256 + tid;

    const float* om = (side ? g_Ro : g_Lo) + (size_t)n * 8;
    float omv[8];
    {
        float4 a = *(const float4*)om;
        float4 b = *(const float4*)(om + 4);
        omv[0]=a.x; omv[1]=a.y; omv[2]=a.z; omv[3]=a.w;
        omv[4]=b.x; omv[5]=b.y; omv[6]=b.z; omv[7]=b.w;
    }

    float hv[16];
#pragma unroll
    for (int h = 0; h < 16; h++) hv[h] = 0.f;
    const float4* yp = (const float4*)(g_y + ((size_t)side * NROW + n) * 128);
#pragma unroll 1
    for (int e = 0; e < 8; e++) {
        float oe = omv[e];
#pragma unroll
        for (int q4 = 0; q4 < 4; q4++) {
            float4 v = yp[e * 4 + q4];
            hv[q4*4+0] = fmaf(oe, v.x, hv[q4*4+0]);
            hv[q4*4+1] = fmaf(oe, v.y, hv[q4*4+1]);
            hv[q4*4+2] = fmaf(oe, v.z, hv[q4*4+2]);
            hv[q4*4+3] = fmaf(oe, v.w, hv[q4*4+3]);
        }
    }
    float* dst = (side ? g_hR : g_hL) + (size_t)n * 16;
#pragma unroll
    for (int q4 = 0; q4 < 4; q4++)
        ((float4*)dst)[q4] = make_float4(hv[q4*4+0], hv[q4*4+1], hv[q4*4+2], hv[q4*4+3]);

#pragma unroll
    for (int h = 0; h < 16; h++) {
        ssum[h][tid] = hv[h];
        ssq [h][tid] = hv[h] * hv[h];
    }
    __syncthreads();
    for (int ofs = 128; ofs > 0; ofs >>= 1) {
        if (tid < ofs) {
#pragma unroll
            for (int h = 0; h < 16; h++) {
                ssum[h][tid] += ssum[h][tid + ofs];
                ssq [h][tid] += ssq [h][tid + ofs];
            }
        }
        __syncthreads();
    }
    if (tid < 16)       g_part[side][chunk][0][tid]      = ssum[tid][0];
    else if (tid < 32)  g_part[side][chunk][1][tid - 16] = ssq [tid - 16][0];
}

// ============================================================================
// K3: BN+elu, expert layer-2 (dense collapse), mixer layer-0 projection.
// grid 256 (32 rows), 256 threads, 3 phases.
// ============================================================================
__global__ void __launch_bounds__(256) k_exp2(
    const float* __restrict__ w2, const float* __restrict__ b2,
    const float* __restrict__ aeg, const float* __restrict__ aebt,
    const float* __restrict__ Wih0m, const float* __restrict__ bih0m)
{
    __shared__ float sW2T[16*132];   // [o][i]
    __shared__ float sb2[128];
    __shared__ float sWp[768];
    __shared__ float sbi[48];
    __shared__ float sg[16], sbt[16];
    __shared__ float sstat[64];      // [side][mean/inv][16]
    __shared__ float su[32*136];
    __shared__ float sz[32*20];

    const int tid = threadIdx.x;
    for (int i = tid; i < 2048; i += 256) {
        int ii = i >> 4, o = i & 15;
        sW2T[o * 132 + ii] = w2[i];
    }
    for (int i = tid; i < 768; i += 256) sWp[i] = Wih0m[i];
    if (tid < 128) sb2[tid] = b2[tid];
    if (tid < 48)  sbi[tid] = bih0m[tid];
    if (tid < 16)  { sg[tid] = aeg[tid]; sbt[tid] = aebt[tid]; }
    if (tid < 32) {
        int side = tid >> 4, h = tid & 15;
        float s = 0.f, q = 0.f;
#pragma unroll
        for (int c = 0; c < 32; c++) {
            s += g_part[side][c][0][h];
            q += g_part[side][c][1][h];
        }
        float mean = s * (1.0f / NROW);
        float var  = q * (1.0f / NROW) - mean * mean;
        sstat[side * 32 + h]      = mean;
        sstat[side * 32 + 16 + h] = rsqrtf(var + 1e-5f);
    }
    __syncthreads();

    const int r = tid >> 3;      // 0..31
    const int n = blockIdx.x * 32 + r;

    {   // ---- phase A: build u (thread = row x h-pair) ----
        const int p = tid & 7;
        const int h0i = 2 * p;
        float2 hl = *(const float2*)(g_hL + (size_t)n * 16 + h0i);
        float2 hr = *(const float2*)(g_hR + (size_t)n * 16 + h0i);
        float vL0 = fmaf(sg[h0i]   * (hl.x - sstat[h0i]),        sstat[16+h0i],   sbt[h0i]);
        float vL1 = fmaf(sg[h0i+1] * (hl.y - sstat[h0i+1]),      sstat[16+h0i+1], sbt[h0i+1]);
        float vR0 = fmaf(sg[h0i]   * (hr.x - sstat[32+h0i]),     sstat[48+h0i],   sbt[h0i]);
        float vR1 = fmaf(sg[h0i+1] * (hr.y - sstat[32+h0i+1]),   sstat[48+h0i+1], sbt[h0i+1]);
        vL0 = (vL0 > 0.f) ? vL0 : (__expf(vL0) - 1.0f);
        vL1 = (vL1 > 0.f) ? vL1 : (__expf(vL1) - 1.0f);
        vR0 = (vR0 > 0.f) ? vR0 : (__expf(vR0) - 1.0f);
        vR1 = (vR1 > 0.f) ? vR1 : (__expf(vR1) - 1.0f);
        float oL[8], oR[8];
        {
            float4 a = *(const float4*)(g_Lo + (size_t)n * 8);
            float4 b = *(const float4*)(g_Lo + (size_t)n * 8 + 4);
            oL[0]=a.x; oL[1]=a.y; oL[2]=a.z; oL[3]=a.w; oL[4]=b.x; oL[5]=b.y; oL[6]=b.z; oL[7]=b.w;
            float4 c = *(const float4*)(g_Ro + (size_t)n * 8);
            float4 d = *(const float4*)(g_Ro + (size_t)n * 8 + 4);
            oR[0]=c.x; oR[1]=c.y; oR[2]=c.z; oR[3]=c.w; oR[4]=d.x; oR[5]=d.y; oR[6]=d.z; oR[7]=d.w;
        }
        float* ur = su + r * 136;
#pragma unroll
        for (int e = 0; e < 8; e++) {
            ur[e*16 + h0i]     = fmaf(oL[e], vL0, oR[e] * vR0);
            ur[e*16 + h0i + 1] = fmaf(oL[e], vL1, oR[e] * vR1);
        }
        if (p == 0) {
#pragma unroll
            for (int e = 0; e < 8; e++) ur[128 + e] = oL[e] + oR[e];
        }
    }
    __syncthreads();

    {   // ---- phase B: z = u @ W2flat + omsum @ b2 (thread = 2 rows x o) ----
        const int g2 = tid >> 4, o = tid & 15;
        const int ra = 2 * g2, rb = ra + 1;
        float acc0 = 0.f, acc1 = 0.f;
        const float* osA = su + ra * 136 + 128;
        const float* osB = su + rb * 136 + 128;
#pragma unroll
        for (int e = 0; e < 8; e++) {
            float w = sb2[e * 16 + o];
            acc0 = fmaf(osA[e], w, acc0);
            acc1 = fmaf(osB[e], w, acc1);
        }
        const float* wrow = sW2T + o * 132;
        const float* uA = su + ra * 136;
        const float* uB = su + rb * 136;
#pragma unroll 4
        for (int i = 0; i < 128; i += 4) {
            float4 w = *(const float4*)(wrow + i);
            float4 a = *(const float4*)(uA + i);
            float4 b = *(const float4*)(uB + i);
            acc0 = fmaf(a.x, w.x, acc0); acc1 = fmaf(b.x, w.x, acc1);
            acc0 = fmaf(a.y, w.y, acc0); acc1 = fmaf(b.y, w.y, acc1);
            acc0 = fmaf(a.z, w.z, acc0); acc1 = fmaf(b.z, w.z, acc1);
            acc0 = fmaf(a.w, w.w, acc0); acc1 = fmaf(b.w, w.w, acc1);
        }
        sz[ra * 20 + o] = acc0;
        sz[rb * 20 + o] = acc1;
    }
    __syncthreads();

    {   // ---- phase C: xw0 = z @ Wp^T + b (thread = row x 6-output slice) ----
        const int sl = tid & 7;
        float zv[16];
        const float4* zp = (const float4*)(sz + r * 20);
#pragma unroll
        for (int q4 = 0; q4 < 4; q4++) {
            float4 v = zp[q4];
            zv[q4*4+0]=v.x; zv[q4*4+1]=v.y; zv[q4*4+2]=v.z; zv[q4*4+3]=v.w;
        }
        float* dst = g_xw0 + (size_t)n * 48 + sl * 6;
#pragma unroll
        for (int jo = 0; jo < 6; jo++) {
            int o = sl * 6 + jo;
            const float* wr = sWp + o * 16;
            float a = sbi[o], bsum = 0.f;
#pragma unroll
            for (int k = 0; k < 16; k += 2) {
                a    = fmaf(zv[k],   wr[k],   a);
                bsum = fmaf(zv[k+1], wr[k+1], bsum);
            }
            dst[jo] = a + bsum;
        }
    }
}

// ============================================================================
// K4: mixer GRU (2 layers, H=16), one warp per batch, approx activations.
// ============================================================================
__global__ void __launch_bounds__(32) k_mixer(
    const float* __restrict__ Whh0, const float* __restrict__ bhh0,
    const float* __restrict__ Wih1, const float* __restrict__ bih1,
    const float* __restrict__ Whh1, const float* __restrict__ bhh1)
{
    const int lane = threadIdx.x;
    const int b    = blockIdx.x;
    const bool hasB = (lane < 16);
    const int gA = lane, gB = 32 + lane;

    float uA0[16], uB0[16], wiA[16], wiB[16], uA1[16], uB1[16];
#pragma unroll
    for (int k = 0; k < 16; k++) {
        uA0[k] = Whh0[gA * 16 + k];
        wiA[k] = Wih1[gA * 16 + k];
        uA1[k] = Whh1[gA * 16 + k];
        uB0[k] = hasB ? Whh0[gB * 16 + k] : 0.f;
        wiB[k] = hasB ? Wih1[gB * 16 + k] : 0.f;
        uB1[k] = hasB ? Whh1[gB * 16 + k] : 0.f;
    }
    float bhA0 = bhh0[gA], bhB0 = hasB ? bhh0[gB] : 0.f;
    float biA1 = bih1[gA], biB1 = hasB ? bih1[gB] : 0.f;
    float bhA1 = bhh1[gA], bhB1 = hasB ? bhh1[gB] : 0.f;

    float h0 = 0.f, h1 = 0.f;
    const float* xp = g_xw0 + (size_t)b * Wn * 48;
    float xA = xp[lane];
    float xB = hasB ? xp[32 + lane] : 0.f;

    for (int t = 0; t < Wn; t++) {
        float cxA = xA, cxB = xB;
        if (t + 1 < Wn) {
            xA = xp[(size_t)(t + 1) * 48 + lane];
            xB = hasB ? xp[(size_t)(t + 1) * 48 + 32 + lane] : 0.f;
        }
        float dAa = bhA0, dAb = 0.f, dBa = bhB0, dBb = 0.f;
#pragma unroll
        for (int k = 0; k < 8; k++) {
            float hk = __shfl_sync(FULLMASK, h0, k);
            dAa = fmaf(uA0[k], hk, dAa);
            dBa = fmaf(uB0[k], hk, dBa);
        }
#pragma unroll
        for (int k = 8; k < 16; k++) {
            float hk = __shfl_sync(FULLMASK, h0, k);
            dAb = fmaf(uA0[k], hk, dAb);
            dBb = fmaf(uB0[k], hk, dBb);
        }
        float dA = dAa + dAb, dB = dBa + dBb;
        float s  = sigm_a(cxA + dA);
        float nv = tanh_a(fmaf(s, dB, cxB));
        float zz = __shfl_sync(FULLMASK, s, 16 + (lane & 15));
        float h0n = fmaf(zz, h0 - nv, nv);
        h0 = hasB ? h0n : h0;

        float xAa = biA1, xAb = 0.f, xBa = biB1, xBb = 0.f;
        float dA1a = bhA1, dA1b = 0.f, dB1a = bhB1, dB1b = 0.f;
#pragma unroll
        for (int k = 0; k < 8; k++) {
            float hk  = __shfl_sync(FULLMASK, h0, k);
            xAa = fmaf(wiA[k], hk, xAa);
            xBa = fmaf(wiB[k], hk, xBa);
            float hk1 = __shfl_sync(FULLMASK, h1, k);
            dA1a = fmaf(uA1[k], hk1, dA1a);
            dB1a = fmaf(uB1[k], hk1, dB1a);
        }
#pragma unroll
        for (int k = 8; k < 16; k++) {
            float hk  = __shfl_sync(FULLMASK, h0, k);
            xAb = fmaf(wiA[k], hk, xAb);
            xBb = fmaf(wiB[k], hk, xBb);
            float hk1 = __shfl_sync(FULLMASK, h1, k);
            dA1b = fmaf(uA1[k], hk1, dA1b);
            dB1b = fmaf(uB1[k], hk1, dB1b);
        }
        float xw1A = xAa + xAb, xw1B = xBa + xBb;
        float gh1A = dA1a + dA1b, gh1B = dB1a + dB1b;
        float s1  = sigm_a(xw1A + gh1A);
        float nv1 = tanh_a(fmaf(s1, gh1B, xw1B));
        float z1  = __shfl_sync(FULLMASK, s1, 16 + (lane & 15));
        float h1n = fmaf(z1, h1 - nv1, nv1);
        h1 = hasB ? h1n : h1;
    }
    if (lane < 16) g_h1fin[b * 16 + lane] = h1;
}

// ============================================================================
// K5a: decoder expert layer-1 + BN + elu (64 rows). One block.
// ============================================================================
__global__ void k_dec1(
    const float* __restrict__ Remote,
    const float* __restrict__ w1, const float* __restrict__ b1,
    const float* __restrict__ gg, const float* __restrict__ bt)
{
    __shared__ float sw1[2176], sb1[128], sh[1024], sstat[32], sgb[32];
    const int tid = threadIdx.x;
    for (int i = tid; i < 2176; i += 1024) sw1[i] = w1[i];
    if (tid < 128) sb1[tid] = b1[tid];
    if (tid < 16) { sgb[tid] = gg[tid]; sgb[16 + tid] = bt[tid]; }
    __syncthreads();

    const int b = tid >> 4, hh = tid & 15;
    {
        float d[17];
#pragma unroll
        for (int k = 0; k < 16; k++) d[k] = g_h1fin[b * 16 + k];
        d[16] = Remote[((size_t)b * Wn + (Wn - 1)) * Fn + (An + TGTn)];
        float acc = 0.f;
#pragma unroll 1
        for (int e = 0; e < 8; e++) {
            float ro = g_Ro[((size_t)b * Wn + (Wn - 1)) * En + e];
            float pe = sb1[e * 16 + hh];
#pragma unroll
            for (int i = 0; i < 17; i++) pe = fmaf(d[i], sw1[e * 272 + i * 16 + hh], pe);
            acc = fmaf(ro, pe, acc);
        }
        sh[tid] = acc;
    }
    __syncthreads();
    if (tid < 16) {
        float s = 0.f, q = 0.f;
        for (int bb = 0; bb < 64; bb++) {
            float v = sh[bb * 16 + tid];
            s += v; q = fmaf(v, v, q);
        }
        float mean = s * (1.0f / 64.0f);
        float var  = q * (1.0f / 64.0f) - mean * mean;
        sstat[tid] = mean;
        sstat[16 + tid] = rsqrtf(var + 1e-5f);
    }
    __syncthreads();
    {
        float v = sh[tid];
        v = fmaf(sgb[hh] * (v - sstat[hh]), sstat[16 + hh], sgb[16 + hh]);
        g_dech[tid] = (v > 0.f) ? v : (__expf(v) - 1.0f);
    }
}

// ============================================================================
// K5b: decoder layer-2 -> out (64 x 128). 16 blocks x 512 threads.
// ============================================================================
#define DEC2_SMEM_BYTES ((16384 + 1024) * 4)
__global__ void __launch_bounds__(512) k_dec2(
    const float* __restrict__ w2, const float* __restrict__ b2,
    float* __restrict__ out)
{
    extern __shared__ float sm[];
    float* sw2 = sm;
    float* sb2 = sm + 16384;
    const int tid = threadIdx.x;
    {
        const float4* w24 = (const float4*)w2;
        float4* sw24 = (float4*)sw2;
        for (int i = tid; i < 4096; i += 512) sw24[i] = w24[i];
        for (int i = tid; i < 1024; i += 512) sb2[i] = b2[i];
    }
    __syncthreads();

    const int b = blockIdx.x * 4 + (tid >> 7);
    const int o = tid & 127;

    float dh[16];
    const float4* hp = (const float4*)(g_dech + b * 16);
#pragma unroll
    for (int q4 = 0; q4 < 4; q4++) {
        float4 v = hp[q4];
        dh[q4*4+0]=v.x; dh[q4*4+1]=v.y; dh[q4*4+2]=v.z; dh[q4*4+3]=v.w;
    }
    float ro[8];
#pragma unroll
    for (int e = 0; e < 8; e++) ro[e] = g_Ro[((size_t)b * Wn + (Wn - 1)) * En + e];

    float acc = 0.f;
#pragma unroll 1
    for (int e = 0; e < 8; e++) {
        float pe = sb2[e * 128 + o];
        const float* wrow = sw2 + e * 2048 + o;
#pragma unroll
        for (int h = 0; h < 16; h++) pe = fmaf(dh[h], wrow[h * 128], pe);
        acc = fmaf(ro[e], pe, acc);
    }
    out[b * 128 + o] = acc;
}

// ============================================================================
// Host launcher
// ============================================================================
extern "C" void kernel_launch(void* const* d_in, const int* in_sizes, int n_in,
                              void* d_out, int out_size)
{
    (void)n_in; (void)out_size;
    const float* P[30];
    for (int i = 0; i < 30; i++) P[i] = (const float*)d_in[i];

    const float *Local = P[0], *Remote = P[1];
    const float *gWih0 = P[2], *gWhh0 = P[3], *gbih0 = P[4], *gbhh0 = P[5];
    const float *gWih1 = P[6], *gWhh1 = P[7], *gbih1 = P[8], *gbhh1 = P[9];
    const float *aew1, *aeb1, *aew2, *aeb2, *aeg, *aebt;
    const float *mdw1, *mdb1, *mdw2, *mdb2, *mdg, *mdbt;
    const float *mWih0, *mWhh0, *mbih0, *mbhh0, *mWih1, *mWhh1, *mbih1, *mbhh1;

    if (in_sizes[10] == 16384) {   // reference-signature order
        aew1 = P[10]; aeb1 = P[11]; aew2 = P[12]; aeb2 = P[13]; aeg = P[14]; aebt = P[15];
        mdw1 = P[16]; mdb1 = P[17]; mdw2 = P[18]; mdb2 = P[19]; mdg = P[20]; mdbt = P[21];
        mWih0 = P[22]; mWhh0 = P[23]; mbih0 = P[24]; mbhh0 = P[25];
        mWih1 = P[26]; mWhh1 = P[27]; mbih1 = P[28]; mbhh1 = P[29];
    } else {                        // setup_inputs dict order
        mWih0 = P[10]; mWhh0 = P[11]; mbih0 = P[12]; mbhh0 = P[13];
        mWih1 = P[14]; mWhh1 = P[15]; mbih1 = P[16]; mbhh1 = P[17];
        aew1 = P[18]; aeb1 = P[19]; aew2 = P[20]; aeb2 = P[21]; aeg = P[22]; aebt = P[23];
        mdw1 = P[24]; mdb1 = P[25]; mdw2 = P[26]; mdb2 = P[27]; mdg = P[28]; mdbt = P[29];
    }

    cudaFuncSetAttribute(k_dec2, cudaFuncAttributeMaxDynamicSharedMemorySize, DEC2_SMEM_BYTES);

    k_ge1<<<384, 256, GE1_SMEM_BYTES>>>(Local, Remote,
                                        gWih0, gWhh0, gbih0, gbhh0,
                                        gWih1, gWhh1, gbih1, gbhh1,
                                        aew1, aeb1);
    k_comb<<<64, 256>>>();
    k_exp2<<<256, 256>>>(aew2, aeb2, aeg, aebt, mWih0, mbih0);
    k_mixer<<<64, 32>>>(mWhh0, mbhh0, mWih1, mbih1, mWhh1, mbhh1);
    k_dec1<<<1, 1024>>>(Remote, mdw1, mdb1, mdg, mdbt);
    k_dec2<<<16, 512, DEC2_SMEM_BYTES>>>(mdw2, mdb2, (float*)d_out);
}